// round 16
// baseline (speedup 1.0000x reference)
#include <cuda_runtime.h>

#define Bn   2
#define Tn   7
#define Hn   128
#define Wn   128
#define Pn   343            // 7*7*7 taps
#define Un   16
#define HW   (Hn*Wn)        // 16384
#define WT   16             // w-tile per block (per h row)
#define HT   2              // h rows per block
#define GH   8              // patch gh rows needed: 7 + HT - 1
#define RL   24             // padded patch row length (WT+6=22 -> 24)
#define TSTR (GH*RL)        // per-t stride (floats)
#define CSTR (Tn*TSTR)      // per-channel stride (floats)

// R16 = R14 (best: 123.4us) + prefetch.global.L2 of the NEXT row's 7 taps.
// Prefetch has no dst reg / no scoreboard -> in-flight DRAM requests no
// longer capped by reg-staged MLP (the cap that pinned DRAM at ~74% across
// R1-R15). Next-row offsets are 0..6MB from the advanced fp -> fit the
// 24-bit LDG immediate, no extra base register, regs stay <=73 (7 blocks).
// Subsequent LDG.128s hit L2 (~250cyc) instead of DRAM (~577+).
// Fused softmax-without-max: filt (719MB) streamed exactly once.
__global__ __launch_bounds__(128, 7)
void dynfilt_kernel(const float* __restrict__ x,
                    const float* __restrict__ filt,
                    float* __restrict__ out)
{
    __shared__ float sm[3 * CSTR];   // 16.1 KB

    const int bx    = blockIdx.x;
    const int wq    = bx & 7;            // w eighth (8 tiles of 16)
    const int hp    = (bx >> 3) & 63;    // h pair index
    const int b     = bx >> 9;           // batch
    const int tid   = threadIdx.x;
    const int wg    = tid & 3;           // 0..3 -> w0 = 4*wg
    const int hh    = (tid >> 2) & 1;    // 0..1
    const int u     = tid >> 3;          // 0..15
    const int wbase = wq * WT;
    const int h0    = hp * HT;
    const int h     = h0 + hh;

    // ---- stage x patches (fp32): sm[((c*7+t)*8+g)*24 + j]
    //      g = gh-(h0-3) in [0,8), j = gw-(wbase-3) in [0,22), zero pad ----
    for (int idx = tid; idx < 3 * CSTR; idx += 128) {
        int j = idx % RL;
        int g = (idx / RL) % GH;
        int t = (idx / TSTR) % Tn;
        int c = idx / CSTR;
        int gh = h0 - 3 + g;
        int gw = wbase - 3 + j;
        float v = 0.f;
        if (j < WT + 6 && (unsigned)gh < (unsigned)Hn && (unsigned)gw < (unsigned)Wn)
            v = x[(((size_t)(b * 3 + c) * Tn + t) * Hn + gh) * Wn + gw];
        sm[idx] = v;
    }
    __syncthreads();

    float acc0[4] = {0.f, 0.f, 0.f, 0.f};   // channel 0, w0..w0+3
    float acc1[4] = {0.f, 0.f, 0.f, 0.f};
    float acc2[4] = {0.f, 0.f, 0.f, 0.f};
    float lsum[4] = {0.f, 0.f, 0.f, 0.f};

    // filt[b, p, u, h, w]; per-tap stride = Un*HW elems (1 MB).
    const size_t TAP = (size_t)Un * HW;
    const float* fp = filt + (((size_t)b * Pn) * Un + (size_t)u) * HW
                           + (size_t)h * Wn + wbase + 4 * wg;

    // warm L2 for row 0 (row 1 gets prefetched at end of iteration 0)
    #pragma unroll
    for (int k = 0; k < 7; ++k)
        asm volatile("prefetch.global.L2 [%0];" :: "l"(fp + (size_t)k * TAP));

    #pragma unroll 1
    for (int r = 0; r < 49; ++r) {
        const int t  = r / 7;
        const int kh = r % 7;
        // patch row for (t, kh) at this thread's h: g = hh + kh
        const float* srow = sm + t * TSTR + (hh + kh) * RL + 4 * wg;  // 16B aligned

        // ---- phase A: stage 4 taps (LDG.128) + patch window [0..7] ----
        float4 f0 = __ldcs((const float4*)(fp + 0 * TAP));
        float4 f1 = __ldcs((const float4*)(fp + 1 * TAP));
        float4 f2 = __ldcs((const float4*)(fp + 2 * TAP));
        float4 f3 = __ldcs((const float4*)(fp + 3 * TAP));

        float pw[3][12];
        #pragma unroll
        for (int c = 0; c < 3; ++c) {
            float4 q0 = *(const float4*)(srow + c * CSTR);
            float4 q1 = *(const float4*)(srow + c * CSTR + 4);
            pw[c][0] = q0.x; pw[c][1] = q0.y; pw[c][2] = q0.z; pw[c][3] = q0.w;
            pw[c][4] = q1.x; pw[c][5] = q1.y; pw[c][6] = q1.z; pw[c][7] = q1.w;
        }

        float4 fq[4] = {f0, f1, f2, f3};
        #pragma unroll
        for (int kw = 0; kw < 4; ++kw) {
            float e0 = __expf(fq[kw].x);
            float e1 = __expf(fq[kw].y);
            float e2 = __expf(fq[kw].z);
            float e3 = __expf(fq[kw].w);
            lsum[0] += e0; lsum[1] += e1; lsum[2] += e2; lsum[3] += e3;
            acc0[0] += e0 * pw[0][kw];     acc0[1] += e1 * pw[0][kw + 1];
            acc0[2] += e2 * pw[0][kw + 2]; acc0[3] += e3 * pw[0][kw + 3];
            acc1[0] += e0 * pw[1][kw];     acc1[1] += e1 * pw[1][kw + 1];
            acc1[2] += e2 * pw[1][kw + 2]; acc1[3] += e3 * pw[1][kw + 3];
            acc2[0] += e0 * pw[2][kw];     acc2[1] += e1 * pw[2][kw + 1];
            acc2[2] += e2 * pw[2][kw + 2]; acc2[3] += e3 * pw[2][kw + 3];
        }

        // ---- phase B: 3 taps + patch window [8..11] ----
        float4 g0 = __ldcs((const float4*)(fp + 4 * TAP));
        float4 g1 = __ldcs((const float4*)(fp + 5 * TAP));
        float4 g2 = __ldcs((const float4*)(fp + 6 * TAP));

        #pragma unroll
        for (int c = 0; c < 3; ++c) {
            float4 q2 = *(const float4*)(srow + c * CSTR + 8);
            pw[c][8] = q2.x; pw[c][9] = q2.y; pw[c][10] = q2.z; pw[c][11] = q2.w;
        }

        float4 gq[3] = {g0, g1, g2};
        #pragma unroll
        for (int k = 0; k < 3; ++k) {
            int kw = k + 4;
            float e0 = __expf(gq[k].x);
            float e1 = __expf(gq[k].y);
            float e2 = __expf(gq[k].z);
            float e3 = __expf(gq[k].w);
            lsum[0] += e0; lsum[1] += e1; lsum[2] += e2; lsum[3] += e3;
            acc0[0] += e0 * pw[0][kw];     acc0[1] += e1 * pw[0][kw + 1];
            acc0[2] += e2 * pw[0][kw + 2]; acc0[3] += e3 * pw[0][kw + 3];
            acc1[0] += e0 * pw[1][kw];     acc1[1] += e1 * pw[1][kw + 1];
            acc1[2] += e2 * pw[1][kw + 2]; acc1[3] += e3 * pw[1][kw + 3];
            acc2[0] += e0 * pw[2][kw];     acc2[1] += e1 * pw[2][kw + 1];
            acc2[2] += e2 * pw[2][kw + 2]; acc2[3] += e3 * pw[2][kw + 3];
        }

        fp += 7 * TAP;

        // ---- prefetch NEXT row's 7 taps into L2 (no reg, no scoreboard).
        //      Offsets 0..6*TAP (<= 6MB) from the advanced fp fit the LDG
        //      immediate window. Lead time ~ one row iteration >> DRAM lat.
        if (r < 48) {
            #pragma unroll
            for (int k = 0; k < 7; ++k)
                asm volatile("prefetch.global.L2 [%0];"
                             :: "l"(fp + (size_t)k * TAP));
        }
    }

    // ---- epilogue: normalize + pixel shuffle ----
    // u -> (ur = u/4, uc = u%4); thread w's are wbase+4wg+i -> col 4w+uc.
    const int ur = u >> 2, uc = u & 3;
    const int Ho = Hn * 4, Wo = Wn * 4;
    const size_t cstride = (size_t)Ho * Wo;
    size_t obase = ((size_t)(b * 3) * Ho + (4 * h + ur)) * Wo
                 + (size_t)4 * (wbase + 4 * wg) + uc;

    #pragma unroll
    for (int i = 0; i < 4; ++i) {
        float inv = 1.f / lsum[i];
        out[obase + 4 * i]                = acc0[i] * inv;
        out[obase + 4 * i + cstride]      = acc1[i] * inv;
        out[obase + 4 * i + 2 * cstride]  = acc2[i] * inv;
    }
}

extern "C" void kernel_launch(void* const* d_in, const int* in_sizes, int n_in,
                              void* d_out, int out_size)
{
    const float* x    = (const float*)d_in[0];   // [2,3,7,128,128]
    const float* filt = (const float*)d_in[1];   // [2,343,16,128,128]
    float* out        = (float*)d_out;           // [2,3,512,512]

    // grid = B * (H/HT) * (W/WT) = 2*64*8 = 1024 blocks, 128 threads.
    // 148 SMs x 7 resident (16.1KB smem, <=73 regs) = 1036 >= 1024:
    // single wave, 1.2% imbalance. No carveout attribute (R12 lesson).
    dynfilt_kernel<<<Bn * (Hn / HT) * (Wn / WT), 128>>>(x, filt, out);
}

// round 17
// speedup vs baseline: 1.0327x; 1.0327x over previous
#include <cuda_runtime.h>

#define Bn   2
#define Tn   7
#define Hn   128
#define Wn   128
#define Pn   343            // 7*7*7 taps
#define Un   16
#define HW   (Hn*Wn)        // 16384
#define WT   16             // w-tile per block (per h row)
#define HT   2              // h rows per block
#define GH   8              // patch gh rows needed: 7 + HT - 1
#define RL   24             // padded patch row length (WT+6=22 -> 24)
#define TSTR (GH*RL)        // per-t stride (floats)
#define CSTR (Tn*TSTR)      // per-channel stride (floats)

// R17 = R14 (best: 123.4us) + per-block ROW-LOOP ROTATION.
// R14/R15/R16 all pin DRAM at exactly 74.4% (5.9TB/s) regardless of request
// shape / occupancy / prefetch -> the residual idle is temporal hotspotting:
// all 1024 blocks stream taps p=0..342 in lockstep, so the chip hammers a
// ~2-4MB slice of filt at a time. Fix: block starts at row r0 = f(bx) and
// wraps (softmax sums are order-independent) -> instantaneous footprint
// spreads over ~100MB, all channels/banks active. fp rebuilt per row (1 IMAD);
// in-row tap offsets stay compile-time immediates. Prefetch dropped (R16).
__global__ __launch_bounds__(128, 7)
void dynfilt_kernel(const float* __restrict__ x,
                    const float* __restrict__ filt,
                    float* __restrict__ out)
{
    __shared__ float sm[3 * CSTR];   // 16.1 KB

    const int bx    = blockIdx.x;
    const int wq    = bx & 7;            // w eighth (8 tiles of 16)
    const int hp    = (bx >> 3) & 63;    // h pair index
    const int b     = bx >> 9;           // batch
    const int tid   = threadIdx.x;
    const int wg    = tid & 3;           // 0..3 -> w0 = 4*wg
    const int hh    = (tid >> 2) & 1;    // 0..1
    const int u     = tid >> 3;          // 0..15
    const int wbase = wq * WT;
    const int h0    = hp * HT;
    const int h     = h0 + hh;

    // ---- stage x patches (fp32): sm[((c*7+t)*8+g)*24 + j]
    //      g = gh-(h0-3) in [0,8), j = gw-(wbase-3) in [0,22), zero pad ----
    for (int idx = tid; idx < 3 * CSTR; idx += 128) {
        int j = idx % RL;
        int g = (idx / RL) % GH;
        int t = (idx / TSTR) % Tn;
        int c = idx / CSTR;
        int gh = h0 - 3 + g;
        int gw = wbase - 3 + j;
        float v = 0.f;
        if (j < WT + 6 && (unsigned)gh < (unsigned)Hn && (unsigned)gw < (unsigned)Wn)
            v = x[(((size_t)(b * 3 + c) * Tn + t) * Hn + gh) * Wn + gw];
        sm[idx] = v;
    }
    __syncthreads();

    float acc0[4] = {0.f, 0.f, 0.f, 0.f};   // channel 0, w0..w0+3
    float acc1[4] = {0.f, 0.f, 0.f, 0.f};
    float acc2[4] = {0.f, 0.f, 0.f, 0.f};
    float lsum[4] = {0.f, 0.f, 0.f, 0.f};

    // filt[b, p, u, h, w]; per-tap stride = Un*HW elems (1 MB).
    const size_t TAP = (size_t)Un * HW;
    const float* fbase = filt + (((size_t)b * Pn) * Un + (size_t)u) * HW
                              + (size_t)h * Wn + wbase + 4 * wg;

    // de-phase: start row differs per block; 49 phase groups chip-wide.
    const int r0 = bx % 49;

    #pragma unroll 1
    for (int i = 0; i < 49; ++i) {
        int r = r0 + i;
        if (r >= 49) r -= 49;

        const int t  = r / 7;
        const int kh = r % 7;
        const float* fp   = fbase + (size_t)r * (7 * TAP);
        const float* srow = sm + t * TSTR + (hh + kh) * RL + 4 * wg;  // 16B aligned

        // ---- phase A: stage 4 taps (LDG.128) + patch window [0..7] ----
        float4 f0 = __ldcs((const float4*)(fp + 0 * TAP));
        float4 f1 = __ldcs((const float4*)(fp + 1 * TAP));
        float4 f2 = __ldcs((const float4*)(fp + 2 * TAP));
        float4 f3 = __ldcs((const float4*)(fp + 3 * TAP));

        float pw[3][12];
        #pragma unroll
        for (int c = 0; c < 3; ++c) {
            float4 q0 = *(const float4*)(srow + c * CSTR);
            float4 q1 = *(const float4*)(srow + c * CSTR + 4);
            pw[c][0] = q0.x; pw[c][1] = q0.y; pw[c][2] = q0.z; pw[c][3] = q0.w;
            pw[c][4] = q1.x; pw[c][5] = q1.y; pw[c][6] = q1.z; pw[c][7] = q1.w;
        }

        float4 fq[4] = {f0, f1, f2, f3};
        #pragma unroll
        for (int kw = 0; kw < 4; ++kw) {
            float e0 = __expf(fq[kw].x);
            float e1 = __expf(fq[kw].y);
            float e2 = __expf(fq[kw].z);
            float e3 = __expf(fq[kw].w);
            lsum[0] += e0; lsum[1] += e1; lsum[2] += e2; lsum[3] += e3;
            acc0[0] += e0 * pw[0][kw];     acc0[1] += e1 * pw[0][kw + 1];
            acc0[2] += e2 * pw[0][kw + 2]; acc0[3] += e3 * pw[0][kw + 3];
            acc1[0] += e0 * pw[1][kw];     acc1[1] += e1 * pw[1][kw + 1];
            acc1[2] += e2 * pw[1][kw + 2]; acc1[3] += e3 * pw[1][kw + 3];
            acc2[0] += e0 * pw[2][kw];     acc2[1] += e1 * pw[2][kw + 1];
            acc2[2] += e2 * pw[2][kw + 2]; acc2[3] += e3 * pw[2][kw + 3];
        }

        // ---- phase B: 3 taps + patch window [8..11] ----
        float4 g0 = __ldcs((const float4*)(fp + 4 * TAP));
        float4 g1 = __ldcs((const float4*)(fp + 5 * TAP));
        float4 g2 = __ldcs((const float4*)(fp + 6 * TAP));

        #pragma unroll
        for (int c = 0; c < 3; ++c) {
            float4 q2 = *(const float4*)(srow + c * CSTR + 8);
            pw[c][8] = q2.x; pw[c][9] = q2.y; pw[c][10] = q2.z; pw[c][11] = q2.w;
        }

        float4 gq[3] = {g0, g1, g2};
        #pragma unroll
        for (int k = 0; k < 3; ++k) {
            int kw = k + 4;
            float e0 = __expf(gq[k].x);
            float e1 = __expf(gq[k].y);
            float e2 = __expf(gq[k].z);
            float e3 = __expf(gq[k].w);
            lsum[0] += e0; lsum[1] += e1; lsum[2] += e2; lsum[3] += e3;
            acc0[0] += e0 * pw[0][kw];     acc0[1] += e1 * pw[0][kw + 1];
            acc0[2] += e2 * pw[0][kw + 2]; acc0[3] += e3 * pw[0][kw + 3];
            acc1[0] += e0 * pw[1][kw];     acc1[1] += e1 * pw[1][kw + 1];
            acc1[2] += e2 * pw[1][kw + 2]; acc1[3] += e3 * pw[1][kw + 3];
            acc2[0] += e0 * pw[2][kw];     acc2[1] += e1 * pw[2][kw + 1];
            acc2[2] += e2 * pw[2][kw + 2]; acc2[3] += e3 * pw[2][kw + 3];
        }
    }

    // ---- epilogue: normalize + pixel shuffle ----
    // u -> (ur = u/4, uc = u%4); thread w's are wbase+4wg+i -> col 4w+uc.
    const int ur = u >> 2, uc = u & 3;
    const int Ho = Hn * 4, Wo = Wn * 4;
    const size_t cstride = (size_t)Ho * Wo;
    size_t obase = ((size_t)(b * 3) * Ho + (4 * h + ur)) * Wo
                 + (size_t)4 * (wbase + 4 * wg) + uc;

    #pragma unroll
    for (int i = 0; i < 4; ++i) {
        float inv = 1.f / lsum[i];
        out[obase + 4 * i]                = acc0[i] * inv;
        out[obase + 4 * i + cstride]      = acc1[i] * inv;
        out[obase + 4 * i + 2 * cstride]  = acc2[i] * inv;
    }
}

extern "C" void kernel_launch(void* const* d_in, const int* in_sizes, int n_in,
                              void* d_out, int out_size)
{
    const float* x    = (const float*)d_in[0];   // [2,3,7,128,128]
    const float* filt = (const float*)d_in[1];   // [2,343,16,128,128]
    float* out        = (float*)d_out;           // [2,3,512,512]

    // grid = B * (H/HT) * (W/WT) = 2*64*8 = 1024 blocks, 128 threads.
    // 148 SMs x 7 resident (16.1KB smem, <=73 regs) = 1036 >= 1024:
    // single wave. No carveout attribute (R12 lesson).
    dynfilt_kernel<<<Bn * (Hn / HT) * (Wn / WT), 128>>>(x, filt, out);
}